// round 15
// baseline (speedup 1.0000x reference)
#include <cuda_runtime.h>
#include <cuda_fp16.h>

#define F 64
#define MAX_N 50176
#define CAP 128            // max in-degree capacity per node (avg 16, tail ~45)
#define XLD 72             // padded half-stride for W smem tile

// ---- scratch (static device globals; no runtime allocation) ----
__device__ __half2 g_hh[MAX_N * 32];   // h = x @ W, fp16 (128 B per row)
__device__ float g_as[MAX_N];          // alpha_src = h @ a_src
__device__ float g_ad[MAX_N];          // alpha_dst = h @ a_dst
__device__ int   g_cursor[MAX_N];      // per-node fill cursor (= final count)
__device__ int2  g_bin[MAX_N * CAP];   // packed (src<<7 byte-offset, exp bits)

// ---------------------------------------------------------------
// h = x @ W via HMMA (m16n8k16) — R10 config. A-fragments loaded
// directly from global as float2 (16 independent LDG.64/thread).
// W staged in smem. 64 rows x 64 cols per block, 128 threads.
// Alphas computed from the accumulators in the epilogue.
// ---------------------------------------------------------------
__global__ __launch_bounds__(128) void k_hgemm(
    const float* __restrict__ x, const float* __restrict__ W,
    const float* __restrict__ a_src, const float* __restrict__ a_dst, int N)
{
    __shared__ __half wt[F][XLD];     // W transposed fp16 [n][k]
    int tid  = threadIdx.x;
    int warp = tid >> 5;
    int lane = tid & 31;
    int g = lane >> 2;        // group id (0..7)
    int t = lane & 3;         // thread in group
    int row0 = blockIdx.x * 64 + warp * 16;
    int r1 = row0 + g;
    int r2 = r1 + 8;

    // issue all 16 A-fragment loads up front (independent LDG.64s)
    float2 xa[16];
    #pragma unroll
    for (int ks = 0; ks < 4; ks++) {
        int c0 = ks * 16 + 2 * t;
        xa[ks * 4 + 0] = (r1 < N) ? *(const float2*)&x[r1 * F + c0]     : make_float2(0.f, 0.f);
        xa[ks * 4 + 1] = (r2 < N) ? *(const float2*)&x[r2 * F + c0]     : make_float2(0.f, 0.f);
        xa[ks * 4 + 2] = (r1 < N) ? *(const float2*)&x[r1 * F + c0 + 8] : make_float2(0.f, 0.f);
        xa[ks * 4 + 3] = (r2 < N) ? *(const float2*)&x[r2 * F + c0 + 8] : make_float2(0.f, 0.f);
    }

    // zero fill-cursors (grid*128 >= N; ordered before k_fill by kernel boundary)
    int zi = blockIdx.x * 128 + tid;
    if (zi < N) g_cursor[zi] = 0;

    // W[k][n] -> wt[n][k] fp16 (coalesced read; tiny, L2-hot)
    for (int i = tid; i < F * F; i += 128) {
        int k = i >> 6, n = i & 63;
        wt[n][k] = __float2half_rn(W[i]);
    }
    __syncthreads();

    // convert A fragments to packed half2
    unsigned A[16];
    #pragma unroll
    for (int i = 0; i < 16; i++) {
        __half2 hv = __floats2half2_rn(xa[i].x, xa[i].y);
        A[i] = *(unsigned*)&hv;
    }

    float acc[8][4];
    #pragma unroll
    for (int nf = 0; nf < 8; nf++)
        #pragma unroll
        for (int c = 0; c < 4; c++) acc[nf][c] = 0.f;

    #pragma unroll
    for (int ks = 0; ks < 4; ks++) {
        int ak = ks * 16 + 2 * t;
        #pragma unroll
        for (int nf = 0; nf < 8; nf++) {
            int bn = nf * 8 + g;
            unsigned b0 = *(const unsigned*)&wt[bn][ak];
            unsigned b1 = *(const unsigned*)&wt[bn][ak + 8];
            asm volatile(
                "mma.sync.aligned.m16n8k16.row.col.f32.f16.f16.f32 "
                "{%0,%1,%2,%3}, {%4,%5,%6,%7}, {%8,%9}, {%0,%1,%2,%3};"
                : "+f"(acc[nf][0]), "+f"(acc[nf][1]), "+f"(acc[nf][2]), "+f"(acc[nf][3])
                : "r"(A[ks * 4 + 0]), "r"(A[ks * 4 + 1]),
                  "r"(A[ks * 4 + 2]), "r"(A[ks * 4 + 3]),
                  "r"(b0), "r"(b1));
        }
    }

    // epilogue: thread (g,t) holds rows r1,r2; cols nf*8+2t, nf*8+2t+1.
    float s1 = 0.f, d1 = 0.f, s2 = 0.f, d2 = 0.f;
    #pragma unroll
    for (int nf = 0; nf < 8; nf++) {
        int c = nf * 8 + 2 * t;
        float sa0 = a_src[c], sa1 = a_src[c + 1];
        float da0 = a_dst[c], da1 = a_dst[c + 1];
        s1 += acc[nf][0] * sa0 + acc[nf][1] * sa1;
        d1 += acc[nf][0] * da0 + acc[nf][1] * da1;
        s2 += acc[nf][2] * sa0 + acc[nf][3] * sa1;
        d2 += acc[nf][2] * da0 + acc[nf][3] * da1;
        int cc = nf * 4 + t;     // half2 column index
        if (r1 < N) g_hh[r1 * 32 + cc] = __floats2half2_rn(acc[nf][0], acc[nf][1]);
        if (r2 < N) g_hh[r2 * 32 + cc] = __floats2half2_rn(acc[nf][2], acc[nf][3]);
    }
    #pragma unroll
    for (int off = 2; off; off >>= 1) {
        s1 += __shfl_down_sync(0xffffffffu, s1, off, 4);
        d1 += __shfl_down_sync(0xffffffffu, d1, off, 4);
        s2 += __shfl_down_sync(0xffffffffu, s2, off, 4);
        d2 += __shfl_down_sync(0xffffffffu, d2, off, 4);
    }
    if (t == 0) {
        if (r1 < N) { g_as[r1] = s1; g_ad[r1] = d1; }
        if (r2 < N) { g_as[r2] = s2; g_ad[r2] = d2; }
    }
}

// ---------------------------------------------------------------
// fill bins: 4 edges per thread. int4 index loads, all alpha
// gathers issued before any exp/atomic (max MLP on the latency path).
// ex = exp(leakyrelu(as[s]+ad[d])); append (s<<7, ex) to dst's slots.
// ---------------------------------------------------------------
__global__ void k_fill(const int* __restrict__ ei, int E) {
    int i0 = (blockIdx.x * blockDim.x + threadIdx.x) * 4;
    if (i0 + 4 <= E) {
        int4 ss = *(const int4*)&ei[i0];
        int4 dd = *(const int4*)&ei[E + i0];
        // issue all 8 alpha gathers as independent loads
        float as0 = g_as[ss.x], as1 = g_as[ss.y], as2 = g_as[ss.z], as3 = g_as[ss.w];
        float ad0 = g_ad[dd.x], ad1 = g_ad[dd.y], ad2 = g_ad[dd.z], ad3 = g_ad[dd.w];
        float v0 = as0 + ad0, v1 = as1 + ad1, v2 = as2 + ad2, v3 = as3 + ad3;
        v0 = (v0 > 0.f) ? v0 : 0.2f * v0;
        v1 = (v1 > 0.f) ? v1 : 0.2f * v1;
        v2 = (v2 > 0.f) ? v2 : 0.2f * v2;
        v3 = (v3 > 0.f) ? v3 : 0.2f * v3;
        float e0 = __expf(v0), e1 = __expf(v1), e2 = __expf(v2), e3 = __expf(v3);
        int p0 = atomicAdd(&g_cursor[dd.x], 1);
        int p1 = atomicAdd(&g_cursor[dd.y], 1);
        int p2 = atomicAdd(&g_cursor[dd.z], 1);
        int p3 = atomicAdd(&g_cursor[dd.w], 1);
        g_bin[dd.x * CAP + p0] = make_int2(ss.x << 7, __float_as_int(e0));
        g_bin[dd.y * CAP + p1] = make_int2(ss.y << 7, __float_as_int(e1));
        g_bin[dd.z * CAP + p2] = make_int2(ss.z << 7, __float_as_int(e2));
        g_bin[dd.w * CAP + p3] = make_int2(ss.w << 7, __float_as_int(e3));
    } else {
        for (int i = i0; i < E; i++) {
            int s = ei[i], d = ei[E + i];
            float v = g_as[s] + g_ad[d];
            v = (v > 0.f) ? v : 0.2f * v;
            float ex = __expf(v);
            int p = atomicAdd(&g_cursor[d], 1);
            g_bin[d * CAP + p] = make_int2(s << 7, __float_as_int(ex));
        }
    }
}

// ---------------------------------------------------------------
// gather: one warp per node; half-warp hi owns edge j+hi, lane owns
// 4 features (uint2, byte-offset addressing). Main loop 16 edges/trip
// (8 independent bin->h chains per half). Merge via shfl_xor(16).
// ---------------------------------------------------------------
__global__ __launch_bounds__(256) void k_gather(
    float* __restrict__ out, const float* __restrict__ bias, int N)
{
    int d = (blockIdx.x * 256 + threadIdx.x) >> 5;
    int lane = threadIdx.x & 31;
    if (d >= N) return;
    int hi = lane >> 4;       // which edge of the pair
    int fl = lane & 15;       // feature quarter: features 4*fl .. 4*fl+3
    const char* hb = (const char*)g_hh + fl * 8;   // lane-fixed base

    float4 acc = make_float4(0.f, 0.f, 0.f, 0.f);
    float den = 0.f;
    if (hi == 0) {            // self loop counted once (half 0 only)
        float vs = g_as[d] + g_ad[d];
        vs = (vs > 0.f) ? vs : 0.2f * vs;
        float e0 = __expf(vs);
        uint2 hv = *(const uint2*)(hb + (d << 7));
        float2 u0 = __half22float2(*(__half2*)&hv.x);
        float2 u1 = __half22float2(*(__half2*)&hv.y);
        acc = make_float4(e0 * u0.x, e0 * u0.y, e0 * u1.x, e0 * u1.y);
        den = e0;
    }

    const int2* bin = &g_bin[d * CAP];
    int cnt = g_cursor[d];

    auto proc = [&](int2 m) {
        float ej = __int_as_float(m.y);
        uint2 hv = *(const uint2*)(hb + m.x);
        float2 u0 = __half22float2(*(__half2*)&hv.x);
        float2 u1 = __half22float2(*(__half2*)&hv.y);
        acc.x += ej * u0.x; acc.y += ej * u0.y;
        acc.z += ej * u1.x; acc.w += ej * u1.y;
        den += ej;
    };

    int j = 0;
    for (; j + 16 <= cnt; j += 16) {
        int2 m0 = bin[j      + hi];
        int2 m1 = bin[j + 2  + hi];
        int2 m2 = bin[j + 4  + hi];
        int2 m3 = bin[j + 6  + hi];
        int2 m4 = bin[j + 8  + hi];
        int2 m5 = bin[j + 10 + hi];
        int2 m6 = bin[j + 12 + hi];
        int2 m7 = bin[j + 14 + hi];
        proc(m0); proc(m1); proc(m2); proc(m3);
        proc(m4); proc(m5); proc(m6); proc(m7);
    }
    for (; j + 2 <= cnt; j += 2) {
        proc(bin[j + hi]);
    }
    if (j < cnt) {            // odd leftover: half 1 contributes 0
        int2 m = bin[j];
        if (hi) m.y = 0;
        proc(m);
    }

    // merge the two halves
    den   += __shfl_xor_sync(0xffffffffu, den,   16);
    acc.x += __shfl_xor_sync(0xffffffffu, acc.x, 16);
    acc.y += __shfl_xor_sync(0xffffffffu, acc.y, 16);
    acc.z += __shfl_xor_sync(0xffffffffu, acc.z, 16);
    acc.w += __shfl_xor_sync(0xffffffffu, acc.w, 16);

    if (hi == 0) {
        float inv = 1.f / den;
        float4 bv = *(const float4*)&bias[fl * 4];
        float4 o = make_float4(acc.x * inv + bv.x, acc.y * inv + bv.y,
                               acc.z * inv + bv.z, acc.w * inv + bv.w);
        *(float4*)&out[d * F + fl * 4] = o;
    }
}

// ---------------------------------------------------------------
extern "C" void kernel_launch(void* const* d_in, const int* in_sizes, int n_in,
                              void* d_out, int out_size) {
    const float* x     = (const float*)d_in[0];
    const float* W     = (const float*)d_in[1];
    const float* a_src = (const float*)d_in[2];
    const float* a_dst = (const float*)d_in[3];
    const float* bias  = (const float*)d_in[4];
    const int*   ei    = (const int*)d_in[5];
    float* out = (float*)d_out;

    int N = in_sizes[0] / F;
    int E = in_sizes[5] / 2;

    k_hgemm <<<(N + 63) / 64, 128>>>(x, W, a_src, a_dst, N);
    k_fill  <<<((E + 3) / 4 + 255) / 256, 256>>>(ei, E);
    k_gather<<<((long long)N * 32 + 255) / 256, 256>>>(out, bias, N);
}

// round 16
// speedup vs baseline: 1.1122x; 1.1122x over previous
#include <cuda_runtime.h>
#include <cuda_fp16.h>

#define F 64
#define MAX_N 50176
#define CAP 128            // max in-degree capacity per node (avg 16, tail ~45)
#define XLD 72             // padded half-stride for W smem tile

// ---- scratch (static device globals; no runtime allocation) ----
__device__ __half2 g_hh[MAX_N * 32];   // h = x @ W, fp16 (128 B per row)
__device__ float g_as[MAX_N];          // alpha_src = h @ a_src
__device__ float g_ad[MAX_N];          // alpha_dst = h @ a_dst
__device__ int   g_cursor[MAX_N];      // per-node fill cursor (= final count)
__device__ int2  g_bin[MAX_N * CAP];   // packed (src<<7 byte-offset, exp bits)

// ---------------------------------------------------------------
// h = x @ W via HMMA (m16n8k16) — R10 config. A-fragments loaded
// directly from global as float2 (16 independent LDG.64/thread).
// W staged in smem. 64 rows x 64 cols per block, 128 threads.
// Alphas computed from the accumulators in the epilogue.
// ---------------------------------------------------------------
__global__ __launch_bounds__(128) void k_hgemm(
    const float* __restrict__ x, const float* __restrict__ W,
    const float* __restrict__ a_src, const float* __restrict__ a_dst, int N)
{
    __shared__ __half wt[F][XLD];     // W transposed fp16 [n][k]
    int tid  = threadIdx.x;
    int warp = tid >> 5;
    int lane = tid & 31;
    int g = lane >> 2;        // group id (0..7)
    int t = lane & 3;         // thread in group
    int row0 = blockIdx.x * 64 + warp * 16;
    int r1 = row0 + g;
    int r2 = r1 + 8;

    // issue all 16 A-fragment loads up front (independent LDG.64s)
    float2 xa[16];
    #pragma unroll
    for (int ks = 0; ks < 4; ks++) {
        int c0 = ks * 16 + 2 * t;
        xa[ks * 4 + 0] = (r1 < N) ? *(const float2*)&x[r1 * F + c0]     : make_float2(0.f, 0.f);
        xa[ks * 4 + 1] = (r2 < N) ? *(const float2*)&x[r2 * F + c0]     : make_float2(0.f, 0.f);
        xa[ks * 4 + 2] = (r1 < N) ? *(const float2*)&x[r1 * F + c0 + 8] : make_float2(0.f, 0.f);
        xa[ks * 4 + 3] = (r2 < N) ? *(const float2*)&x[r2 * F + c0 + 8] : make_float2(0.f, 0.f);
    }

    // zero fill-cursors (grid*128 >= N; ordered before k_fill by kernel boundary)
    int zi = blockIdx.x * 128 + tid;
    if (zi < N) g_cursor[zi] = 0;

    // W[k][n] -> wt[n][k] fp16 (coalesced read; tiny, L2-hot)
    for (int i = tid; i < F * F; i += 128) {
        int k = i >> 6, n = i & 63;
        wt[n][k] = __float2half_rn(W[i]);
    }
    __syncthreads();

    // convert A fragments to packed half2
    unsigned A[16];
    #pragma unroll
    for (int i = 0; i < 16; i++) {
        __half2 hv = __floats2half2_rn(xa[i].x, xa[i].y);
        A[i] = *(unsigned*)&hv;
    }

    float acc[8][4];
    #pragma unroll
    for (int nf = 0; nf < 8; nf++)
        #pragma unroll
        for (int c = 0; c < 4; c++) acc[nf][c] = 0.f;

    #pragma unroll
    for (int ks = 0; ks < 4; ks++) {
        int ak = ks * 16 + 2 * t;
        #pragma unroll
        for (int nf = 0; nf < 8; nf++) {
            int bn = nf * 8 + g;
            unsigned b0 = *(const unsigned*)&wt[bn][ak];
            unsigned b1 = *(const unsigned*)&wt[bn][ak + 8];
            asm volatile(
                "mma.sync.aligned.m16n8k16.row.col.f32.f16.f16.f32 "
                "{%0,%1,%2,%3}, {%4,%5,%6,%7}, {%8,%9}, {%0,%1,%2,%3};"
                : "+f"(acc[nf][0]), "+f"(acc[nf][1]), "+f"(acc[nf][2]), "+f"(acc[nf][3])
                : "r"(A[ks * 4 + 0]), "r"(A[ks * 4 + 1]),
                  "r"(A[ks * 4 + 2]), "r"(A[ks * 4 + 3]),
                  "r"(b0), "r"(b1));
        }
    }

    // epilogue: thread (g,t) holds rows r1,r2; cols nf*8+2t, nf*8+2t+1.
    float s1 = 0.f, d1 = 0.f, s2 = 0.f, d2 = 0.f;
    #pragma unroll
    for (int nf = 0; nf < 8; nf++) {
        int c = nf * 8 + 2 * t;
        float sa0 = a_src[c], sa1 = a_src[c + 1];
        float da0 = a_dst[c], da1 = a_dst[c + 1];
        s1 += acc[nf][0] * sa0 + acc[nf][1] * sa1;
        d1 += acc[nf][0] * da0 + acc[nf][1] * da1;
        s2 += acc[nf][2] * sa0 + acc[nf][3] * sa1;
        d2 += acc[nf][2] * da0 + acc[nf][3] * da1;
        int cc = nf * 4 + t;     // half2 column index
        if (r1 < N) g_hh[r1 * 32 + cc] = __floats2half2_rn(acc[nf][0], acc[nf][1]);
        if (r2 < N) g_hh[r2 * 32 + cc] = __floats2half2_rn(acc[nf][2], acc[nf][3]);
    }
    #pragma unroll
    for (int off = 2; off; off >>= 1) {
        s1 += __shfl_down_sync(0xffffffffu, s1, off, 4);
        d1 += __shfl_down_sync(0xffffffffu, d1, off, 4);
        s2 += __shfl_down_sync(0xffffffffu, s2, off, 4);
        d2 += __shfl_down_sync(0xffffffffu, d2, off, 4);
    }
    if (t == 0) {
        if (r1 < N) { g_as[r1] = s1; g_ad[r1] = d1; }
        if (r2 < N) { g_as[r2] = s2; g_ad[r2] = d2; }
    }
}

// ---------------------------------------------------------------
// fill bins (R14): 2 edges per thread, coalesced int2 index loads.
// ex = exp(leakyrelu(as[s]+ad[d])); append (s<<7, ex) to dst's slots.
// ---------------------------------------------------------------
__global__ void k_fill(const int* __restrict__ ei, int E) {
    int i0 = (blockIdx.x * blockDim.x + threadIdx.x) * 2;
    if (i0 >= E) return;
    if (i0 + 1 < E) {
        int2 ss = *(const int2*)&ei[i0];
        int2 dd = *(const int2*)&ei[E + i0];
        float v0 = g_as[ss.x] + g_ad[dd.x];
        float v1 = g_as[ss.y] + g_ad[dd.y];
        v0 = (v0 > 0.f) ? v0 : 0.2f * v0;
        v1 = (v1 > 0.f) ? v1 : 0.2f * v1;
        float e0 = __expf(v0), e1 = __expf(v1);
        int p0 = atomicAdd(&g_cursor[dd.x], 1);
        g_bin[dd.x * CAP + p0] = make_int2(ss.x << 7, __float_as_int(e0));
        int p1 = atomicAdd(&g_cursor[dd.y], 1);
        g_bin[dd.y * CAP + p1] = make_int2(ss.y << 7, __float_as_int(e1));
    } else {
        int s = ei[i0], d = ei[E + i0];
        float v = g_as[s] + g_ad[d];
        v = (v > 0.f) ? v : 0.2f * v;
        float ex = __expf(v);
        int p = atomicAdd(&g_cursor[d], 1);
        g_bin[d * CAP + p] = make_int2(s << 7, __float_as_int(ex));
    }
}

// ---------------------------------------------------------------
// gather (R14 kernel, 64-thread blocks): one warp per node, 2 edges
// per iter; half-warp hi loads its own int2 bin[j+hi]; lane owns 4
// features (uint2, byte-offset addressing). Merge via shfl_xor(16).
// Small blocks -> fine-grained SM backfill (degree-imbalance fix).
// ---------------------------------------------------------------
__global__ __launch_bounds__(64) void k_gather(
    float* __restrict__ out, const float* __restrict__ bias, int N)
{
    int d = (blockIdx.x * 64 + threadIdx.x) >> 5;
    int lane = threadIdx.x & 31;
    if (d >= N) return;
    int hi = lane >> 4;       // which edge of the pair
    int fl = lane & 15;       // feature quarter: features 4*fl .. 4*fl+3
    const char* hb = (const char*)g_hh + fl * 8;   // lane-fixed base

    float4 acc = make_float4(0.f, 0.f, 0.f, 0.f);
    float den = 0.f;
    if (hi == 0) {            // self loop counted once (half 0 only)
        float vs = g_as[d] + g_ad[d];
        vs = (vs > 0.f) ? vs : 0.2f * vs;
        float e0 = __expf(vs);
        uint2 hv = *(const uint2*)(hb + (d << 7));
        float2 u0 = __half22float2(*(__half2*)&hv.x);
        float2 u1 = __half22float2(*(__half2*)&hv.y);
        acc = make_float4(e0 * u0.x, e0 * u0.y, e0 * u1.x, e0 * u1.y);
        den = e0;
    }

    const int2* bin = &g_bin[d * CAP];
    int cnt = g_cursor[d];

    auto proc = [&](int2 m) {
        float ej = __int_as_float(m.y);
        uint2 hv = *(const uint2*)(hb + m.x);
        float2 u0 = __half22float2(*(__half2*)&hv.x);
        float2 u1 = __half22float2(*(__half2*)&hv.y);
        acc.x += ej * u0.x; acc.y += ej * u0.y;
        acc.z += ej * u1.x; acc.w += ej * u1.y;
        den += ej;
    };

    int j = 0;
    for (; j + 8 <= cnt; j += 8) {
        int2 m0 = bin[j + hi];
        int2 m1 = bin[j + 2 + hi];
        int2 m2 = bin[j + 4 + hi];
        int2 m3 = bin[j + 6 + hi];
        proc(m0); proc(m1); proc(m2); proc(m3);
    }
    for (; j + 2 <= cnt; j += 2) {
        proc(bin[j + hi]);
    }
    if (j < cnt) {            // odd leftover: half 1 contributes 0
        int2 m = bin[j];
        if (hi) m.y = 0;
        proc(m);
    }

    // merge the two halves
    den   += __shfl_xor_sync(0xffffffffu, den,   16);
    acc.x += __shfl_xor_sync(0xffffffffu, acc.x, 16);
    acc.y += __shfl_xor_sync(0xffffffffu, acc.y, 16);
    acc.z += __shfl_xor_sync(0xffffffffu, acc.z, 16);
    acc.w += __shfl_xor_sync(0xffffffffu, acc.w, 16);

    if (hi == 0) {
        float inv = 1.f / den;
        float4 bv = *(const float4*)&bias[fl * 4];
        float4 o = make_float4(acc.x * inv + bv.x, acc.y * inv + bv.y,
                               acc.z * inv + bv.z, acc.w * inv + bv.w);
        *(float4*)&out[d * F + fl * 4] = o;
    }
}

// ---------------------------------------------------------------
extern "C" void kernel_launch(void* const* d_in, const int* in_sizes, int n_in,
                              void* d_out, int out_size) {
    const float* x     = (const float*)d_in[0];
    const float* W     = (const float*)d_in[1];
    const float* a_src = (const float*)d_in[2];
    const float* a_dst = (const float*)d_in[3];
    const float* bias  = (const float*)d_in[4];
    const int*   ei    = (const int*)d_in[5];
    float* out = (float*)d_out;

    int N = in_sizes[0] / F;
    int E = in_sizes[5] / 2;

    k_hgemm <<<(N + 63) / 64, 128>>>(x, W, a_src, a_dst, N);
    k_fill  <<<((E + 1) / 2 + 255) / 256, 256>>>(ei, E);
    k_gather<<<((long long)N * 32 + 63) / 64, 64>>>(out, bias, N);
}